// round 16
// baseline (speedup 1.0000x reference)
#include <cuda_runtime.h>
#include <cuda_fp16.h>
#include <math.h>
#include <stdint.h>

#define L 512
#define LL (L*L)
#define POH 72   // fusedC fp16 gather pitch in HALVES (144B)
#define PW 72    // fp16 tile pitch in WORDS (144 halves; 72 mod 32 == 8)
#define PH 72    // fusedA fp16 staging pitch in HALVES (144B, 16B-aligned)
#define PS 40    // syrk chunk pitch in WORDS (80 halves per row slot, 64 used)

// ---- scratch (device globals; allocation-free contract) ----
__device__ __half   g_gate[(size_t)LL*128]; // frag-major __half2 layout
__device__ __half   g_at  [(size_t)128*LL]; // gated a, fp16, l-dim pair-permuted
__device__ __half   g_o   [(size_t)128*LL]; // einsum output, fp16
__device__ uint32_t g_awh [8192];           // fp16 weights, frag-major (uint2=4 halves)
__device__ uint32_t g_agwh[8192];
__device__ uint32_t g_gwh [8192];
__device__ uint32_t g_owh [8192];

__device__ __forceinline__ float sigmoidf_(float x) { return 1.0f / (1.0f + expf(-x)); }

// pair/k8 permutation (order 0,4,1,5,2,6,3,7)
__device__ __forceinline__ int kperm(int k) {
    return (k & ~7) | (((k & 3) << 1) | ((k >> 2) & 1));
}
// fp16 k16 pair permutation on halves
__device__ __forceinline__ int p16(int k) {
    return (k & ~15) | (((k >> 1) & 3) << 2) | (((k >> 3) & 1) << 1) | (k & 1);
}
// frag-major __half2 index for gate[(row, col even pair)]
__device__ __forceinline__ size_t gate_fi(size_t row, int col) {
    return ((row >> 4) * 16 + (size_t)(col >> 3)) * 64 +
           ((row >> 3) & 1) * 32 + (row & 7) * 4 + ((col & 7) >> 1);
}

// fp16 m16n8k16, fp32 accum
__device__ __forceinline__ void mma16h(float* c, uint32_t a0, uint32_t a1,
                                       uint32_t a2, uint32_t a3,
                                       uint32_t b0, uint32_t b1) {
    asm volatile(
        "mma.sync.aligned.m16n8k16.row.col.f32.f16.f16.f32 "
        "{%0,%1,%2,%3}, {%4,%5,%6,%7}, {%8,%9}, {%0,%1,%2,%3};\n"
        : "+f"(c[0]), "+f"(c[1]), "+f"(c[2]), "+f"(c[3])
        : "r"(a0), "r"(a1), "r"(a2), "r"(a3), "r"(b0), "r"(b1));
}

__device__ __forceinline__ void cpa16(void* dst, const void* src) {
    uint32_t s = (uint32_t)__cvta_generic_to_shared(dst);
    asm volatile("cp.async.cg.shared.global [%0], [%1], 16;\n" :: "r"(s), "l"(src));
}
__device__ __forceinline__ void cpa_commit() { asm volatile("cp.async.commit_group;\n" ::: "memory"); }
template<int N> __device__ __forceinline__ void cpa_wait() {
    asm volatile("cp.async.wait_group %0;\n" :: "n"(N) : "memory");
}

// ============================================================
// K0: pre-convert weights to fp16, FRAGMENT-MAJOR
// ============================================================
__global__ void prep_w(const float* __restrict__ aw, const float* __restrict__ agw,
                       const float* __restrict__ gw, const float* __restrict__ ow) {
    int idx = blockIdx.x * 512 + threadIdx.x;   // 16384 total (4 x 4096 uint2)
    int w = idx >> 12, i = idx & 4095;
    int lane = i & 31, kg = (i >> 5) & 7, g = i >> 8;
    int lr = lane >> 2, lc = lane & 3;
    const float* src = (w == 0) ? aw : (w == 1) ? agw : (w == 2) ? gw : ow;
    uint32_t* dst = (w == 0) ? g_awh : (w == 1) ? g_agwh : (w == 2) ? g_gwh : g_owh;
    int n = g * 8 + lr, k0 = kg * 16 + 2 * lc;
    __half2 lo = __floats2half2_rn(src[n * 128 + k0],     src[n * 128 + k0 + 1]);
    __half2 hi = __floats2half2_rn(src[n * 128 + k0 + 8], src[n * 128 + k0 + 9]);
    dst[i * 2]     = *reinterpret_cast<uint32_t*>(&lo);
    dst[i * 2 + 1] = *reinterpret_cast<uint32_t*>(&hi);
}

// ============================================================
// K1: fused LN(fp16) + dual fp16 GEMM (a,ag) + gating -> g_at
//     + fp16 gate GEMM. 256 thr, 64-row tile.
// ============================================================
__global__ void __launch_bounds__(256, 2)
fusedA(const float* __restrict__ z, const float* __restrict__ ng, const float* __restrict__ nb,
       const float* __restrict__ ab, const float* __restrict__ agb, const float* __restrict__ gb) {
    extern __shared__ uint32_t sm[];
    uint32_t* sZw = sm;                             // 64 x PW words fp16 zn (p16 layout)
    __half2*  sZ2 = reinterpret_cast<__half2*>(sm);
    __half*   sP  = reinterpret_cast<__half*>(sm + 64 * PW);  // [col 128][row PH]
    const int tid = threadIdx.x;
    const int wid = tid >> 5, lane = tid & 31;
    const int lr = lane >> 2, lc = lane & 3;
    const size_t m0 = (size_t)blockIdx.x * 64;

    const uint2* WA = reinterpret_cast<const uint2*>(g_awh);
    const uint2* WQ = reinterpret_cast<const uint2*>(g_agwh);
    const uint2* WG = reinterpret_cast<const uint2*>(g_gwh);
    __half2* GATE2 = reinterpret_cast<__half2*>(g_gate);

    // LayerNorm: warp w handles rows [8w, 8w+8); z loads batched 4-at-a-time (MLP)
    {
        float4 g4 = reinterpret_cast<const float4*>(ng)[lane];
        float4 b4 = reinterpret_cast<const float4*>(nb)[lane];
        const int pp0 = kperm(2 * lane), pp1 = kperm(2 * lane + 1);
#pragma unroll
        for (int hb = 0; hb < 2; hb++) {
            float4 vb[4];
#pragma unroll
            for (int it = 0; it < 4; it++)
                vb[it] = reinterpret_cast<const float4*>(z)[(m0 + wid * 8 + hb * 4 + it) * 32 + lane];
#pragma unroll
            for (int it = 0; it < 4; it++) {
                int row = wid * 8 + hb * 4 + it;
                float4 v = vb[it];
                float s = v.x + v.y + v.z + v.w;
                float q = v.x*v.x + v.y*v.y + v.z*v.z + v.w*v.w;
#pragma unroll
                for (int o = 16; o > 0; o >>= 1) {
                    s += __shfl_xor_sync(0xffffffffu, s, o);
                    q += __shfl_xor_sync(0xffffffffu, q, o);
                }
                float mean = s * (1.0f / 128.0f);
                float var  = q * (1.0f / 128.0f) - mean * mean;
                float rs   = rsqrtf(var + 1e-5f);
                sZ2[row * PW + pp0] = __floats2half2_rn((v.x - mean) * rs * g4.x + b4.x,
                                                        (v.y - mean) * rs * g4.y + b4.y);
                sZ2[row * PW + pp1] = __floats2half2_rn((v.z - mean) * rs * g4.z + b4.z,
                                                        (v.w - mean) * rs * g4.w + b4.w);
            }
        }
    }
    __syncthreads();

    // ---- dual fp16 GEMM: acc_a = zn@a_w^T, acc_q = zn@ag_w^T ----
    float acc_a[4][2][4], acc_q[4][2][4];
#pragma unroll
    for (int mf = 0; mf < 4; mf++)
#pragma unroll
        for (int nf = 0; nf < 2; nf++)
#pragma unroll
            for (int v = 0; v < 4; v++) { acc_a[mf][nf][v] = 0.0f; acc_q[mf][nf][v] = 0.0f; }

#pragma unroll
    for (int kg = 0; kg < 8; kg++) {
        int kb = kg * 8;
        uint32_t a[4][4];
#pragma unroll
        for (int mf = 0; mf < 4; mf++) {
            int row = mf * 16 + lr;
            uint2 lo = *reinterpret_cast<const uint2*>(sZw + row * PW + kb + 2 * lc);
            uint2 hi = *reinterpret_cast<const uint2*>(sZw + (row + 8) * PW + kb + 2 * lc);
            a[mf][0] = lo.x; a[mf][1] = hi.x; a[mf][2] = lo.y; a[mf][3] = hi.y;
        }
#pragma unroll
        for (int nf = 0; nf < 2; nf++) {
            int g = wid * 2 + nf;
            uint2 ba = __ldg(WA + g * 256 + kg * 32 + lane);
            uint2 bq = __ldg(WQ + g * 256 + kg * 32 + lane);
#pragma unroll
            for (int mf = 0; mf < 4; mf++) {
                mma16h(acc_a[mf][nf], a[mf][0], a[mf][1], a[mf][2], a[mf][3], ba.x, ba.y);
                mma16h(acc_q[mf][nf], a[mf][0], a[mf][1], a[mf][2], a[mf][3], bq.x, bq.y);
            }
        }
    }

    // epilogue: P = (a + ab) * sigmoid(q + agb) -> fp16 staged in sP (pair-perm rows)
#pragma unroll
    for (int nf = 0; nf < 2; nf++) {
        int col = wid * 16 + nf * 8 + 2 * lc;
        float ba0 = __ldg(ab + col),  ba1 = __ldg(ab + col + 1);
        float bq0 = __ldg(agb + col), bq1 = __ldg(agb + col + 1);
#pragma unroll
        for (int mf = 0; mf < 4; mf++) {
            int r0 = p16(mf * 16 + lr), r1 = p16(mf * 16 + 8 + lr);
            sP[col * PH + r0]       = __float2half_rn((acc_a[mf][nf][0] + ba0) * sigmoidf_(acc_q[mf][nf][0] + bq0));
            sP[(col + 1) * PH + r0] = __float2half_rn((acc_a[mf][nf][1] + ba1) * sigmoidf_(acc_q[mf][nf][1] + bq1));
            sP[col * PH + r1]       = __float2half_rn((acc_a[mf][nf][2] + ba0) * sigmoidf_(acc_q[mf][nf][2] + bq0));
            sP[(col + 1) * PH + r1] = __float2half_rn((acc_a[mf][nf][3] + ba1) * sigmoidf_(acc_q[mf][nf][3] + bq1));
        }
    }
    __syncthreads();

    // coalesced uint4 store of fp16 a-tile: 128 cols x 64 halves
#pragma unroll
    for (int e = 0; e < 4; e++) {
        int idx = tid + 256 * e;           // 1024 uint4
        int c = idx >> 3, e8 = idx & 7;    // 8 uint4 per col
        uint4 v = *reinterpret_cast<const uint4*>(sP + c * PH + e8 * 8);
        *reinterpret_cast<uint4*>(g_at + (size_t)c * LL + m0 + e8 * 8) = v;
    }

    // ---- fp16 gate GEMM (sZ unmodified) ----
    float acc_g[4][2][4];
#pragma unroll
    for (int mf = 0; mf < 4; mf++)
#pragma unroll
        for (int nf = 0; nf < 2; nf++)
#pragma unroll
            for (int v = 0; v < 4; v++) acc_g[mf][nf][v] = 0.0f;

#pragma unroll
    for (int kg = 0; kg < 8; kg++) {
        int kb = kg * 8;
        uint32_t a[4][4];
#pragma unroll
        for (int mf = 0; mf < 4; mf++) {
            int row = mf * 16 + lr;
            uint2 lo = *reinterpret_cast<const uint2*>(sZw + row * PW + kb + 2 * lc);
            uint2 hi = *reinterpret_cast<const uint2*>(sZw + (row + 8) * PW + kb + 2 * lc);
            a[mf][0] = lo.x; a[mf][1] = hi.x; a[mf][2] = lo.y; a[mf][3] = hi.y;
        }
#pragma unroll
        for (int nf = 0; nf < 2; nf++) {
            int g = wid * 2 + nf;
            uint2 bg = __ldg(WG + g * 256 + kg * 32 + lane);
#pragma unroll
            for (int mf = 0; mf < 4; mf++)
                mma16h(acc_g[mf][nf], a[mf][0], a[mf][1], a[mf][2], a[mf][3], bg.x, bg.y);
        }
    }

    // gate stored frag-major fp16 (coalesced __half2)
#pragma unroll
    for (int nf = 0; nf < 2; nf++) {
        int col = wid * 16 + nf * 8 + 2 * lc;
        float b0v = __ldg(gb + col), b1v = __ldg(gb + col + 1);
#pragma unroll
        for (int mf = 0; mf < 4; mf++) {
            size_t row = m0 + mf * 16 + lr;
            size_t fi = gate_fi(row, col);
            GATE2[fi]      = __floats2half2_rn(sigmoidf_(acc_g[mf][nf][0] + b0v),
                                               sigmoidf_(acc_g[mf][nf][1] + b1v));
            GATE2[fi + 32] = __floats2half2_rn(sigmoidf_(acc_g[mf][nf][2] + b0v),
                                               sigmoidf_(acc_g[mf][nf][3] + b1v));
        }
    }
}

// ============================================================
// K2: fp16 SYRK per channel (m16n8k16, fp32 accum), cp.async
//     double-buffered, k-chunk 64. fp16 output, mirror staged
//     through smem for coalesced stores. 256 thr.
// ============================================================
__global__ void __launch_bounds__(256, 2)
syrk_mma() {
    extern __shared__ uint32_t sm[];   // 2 stages x (A + B), pitch PS words/row
    const int tid  = threadIdx.x;
    const int wid  = tid >> 5, lane = tid & 31;
    const int wm   = wid >> 1, wn = wid & 1;
    const int lr   = lane >> 2, lc = lane & 3;

    const int c = blockIdx.y;
    int rem = blockIdx.x, bi = 0, span = 4;
    while (rem >= span) { rem -= span; span--; bi++; }
    int bj = bi + rem;
    const int i0 = bi * 128, j0 = bj * 128;
    const bool diag = (bi == bj);

    const __half* __restrict__ Ag = g_at + (size_t)c * LL;
    __half* __restrict__ O = g_o + (size_t)c * LL;

    const int STG_SZ = 2 * 128 * PS;   // words per stage (A+B)

    auto load_chunk = [&](int kc, int buf) {
        uint32_t* sA = sm + buf * STG_SZ;
        uint32_t* sB = sA + 128 * PS;
#pragma unroll
        for (int e = 0; e < 4; e++) {
            int idx = tid + 256 * e;
            int r = idx >> 3, c8 = idx & 7;
            cpa16(sA + r * PS + c8 * 4, Ag + (size_t)(i0 + r) * 512 + kc * 64 + c8 * 8);
            if (!diag)
                cpa16(sB + r * PS + c8 * 4, Ag + (size_t)(j0 + r) * 512 + kc * 64 + c8 * 8);
        }
        cpa_commit();
    };

    float acc[2][8][4];
#pragma unroll
    for (int mf = 0; mf < 2; mf++)
#pragma unroll
        for (int nf = 0; nf < 8; nf++)
#pragma unroll
            for (int v = 0; v < 4; v++) acc[mf][nf][v] = 0.0f;

    load_chunk(0, 0);

    for (int kc = 0; kc < 8; kc++) {
        if (kc + 1 < 8) { load_chunk(kc + 1, (kc + 1) & 1); cpa_wait<1>(); }
        else            { cpa_wait<0>(); }
        __syncthreads();
        const uint32_t* sA = sm + (kc & 1) * STG_SZ;
        const uint32_t* sB = diag ? sA : sA + 128 * PS;
#pragma unroll
        for (int g = 0; g < 4; g++) {
            int kb = g * 8;
            uint32_t a[2][4];
#pragma unroll
            for (int mf = 0; mf < 2; mf++) {
                int row = wm * 32 + mf * 16 + lr;
                uint2 lo = *reinterpret_cast<const uint2*>(sA + row * PS + kb + 2 * lc);
                uint2 hi = *reinterpret_cast<const uint2*>(sA + (row + 8) * PS + kb + 2 * lc);
                a[mf][0] = lo.x; a[mf][1] = hi.x; a[mf][2] = lo.y; a[mf][3] = hi.y;
            }
#pragma unroll
            for (int nf = 0; nf < 8; nf++) {
                int col = wn * 64 + nf * 8 + lr;
                uint2 b = *reinterpret_cast<const uint2*>(sB + col * PS + kb + 2 * lc);
                mma16h(acc[0][nf], a[0][0], a[0][1], a[0][2], a[0][3], b.x, b.y);
                mma16h(acc[1][nf], a[1][0], a[1][1], a[1][2], a[1][3], b.x, b.y);
            }
        }
        __syncthreads();
    }

    // direct tile write (fp16 __half2)
#pragma unroll
    for (int mf = 0; mf < 2; mf++) {
#pragma unroll
        for (int nf = 0; nf < 8; nf++) {
            int rowi = i0 + wm * 32 + mf * 16 + lr;
            int colj = j0 + wn * 64 + nf * 8 + 2 * lc;
            *reinterpret_cast<__half2*>(O + (size_t)rowi * 512 + colj) =
                __floats2half2_rn(acc[mf][nf][0], acc[mf][nf][1]);
            *reinterpret_cast<__half2*>(O + (size_t)(rowi + 8) * 512 + colj) =
                __floats2half2_rn(acc[mf][nf][2], acc[mf][nf][3]);
        }
    }

    // mirror: stage transposed fp16 tile in smem, then coalesced uint4 stores
    if (!diag) {
        __half* st = reinterpret_cast<__half*>(sm);   // [col 128][row], pitch 136 halves
#pragma unroll
        for (int mf = 0; mf < 2; mf++) {
#pragma unroll
            for (int nf = 0; nf < 8; nf++) {
                int r  = wm * 32 + mf * 16 + lr;
                int cA = wn * 64 + nf * 8 + 2 * lc;
                st[cA * 136 + r]           = __float2half_rn(acc[mf][nf][0]);
                st[(cA + 1) * 136 + r]     = __float2half_rn(acc[mf][nf][1]);
                st[cA * 136 + r + 8]       = __float2half_rn(acc[mf][nf][2]);
                st[(cA + 1) * 136 + r + 8] = __float2half_rn(acc[mf][nf][3]);
            }
        }
        __syncthreads();
#pragma unroll
        for (int e = 0; e < 8; e++) {
            int idx = tid + 256 * e;        // 2048 uint4
            int col = idx >> 4, e8 = idx & 15;
            uint4 v = *reinterpret_cast<const uint4*>(st + col * 136 + e8 * 8);
            *reinterpret_cast<uint4*>(O + (size_t)(j0 + col) * 512 + i0 + e8 * 8) = v;
        }
    }
}

// ============================================================
// K3: fused gather (fp16 smem, cp.async) + channel-LN + fp16
//     projection + fp16 gating. Direct fragment stores (full
//     32B sectors) — no fp32 staging pass.
// ============================================================
__global__ void __launch_bounds__(256, 3)
fusedC(const float* __restrict__ ong, const float* __restrict__ onb,
       const float* __restrict__ ob, float* __restrict__ out) {
    extern __shared__ uint32_t sm[];
    __half*   sOh = reinterpret_cast<__half*>(sm);  // [c 128][jj 64], pitch POH halves
    uint32_t* sTw = sm + 128 * (POH / 2);           // fp16 [jj 64][p16 c], pitch PW words
    __half*   sTh = reinterpret_cast<__half*>(sTw);
    __shared__ float ps[4][64], pq[4][64], mS[64], rS[64];

    const int tid = threadIdx.x;
    const int wid = tid >> 5, lane = tid & 31;
    const int wm = wid >> 2, wn = wid & 3;
    const int lr = lane >> 2, lc = lane & 3;
    const int i = blockIdx.y, j0 = blockIdx.x * 64;

    const uint2* WO = reinterpret_cast<const uint2*>(g_owh);
    const __half2* GATE2 = reinterpret_cast<const __half2*>(g_gate);

    // gather o tile [c][jj] fp16 via cp.async (deep MLP)
#pragma unroll
    for (int e = 0; e < 4; e++) {
        int idx = tid + 256 * e;       // 1024 x 16B
        int c = idx >> 3, j8 = idx & 7;
        cpa16(sOh + c * POH + j8 * 8, g_o + (size_t)c * LL + (size_t)i * 512 + j0 + j8 * 8);
    }
    cpa_commit();
    cpa_wait<0>();
    __syncthreads();

    // channel reduce (convert fp16 on the fly)
    {
        int col = tid & 63, qtr = tid >> 6;
        float s = 0.0f, q = 0.0f;
#pragma unroll 8
        for (int c = qtr * 32; c < qtr * 32 + 32; c++) {
            float v = __half2float(sOh[c * POH + col]);
            s += v; q += v * v;
        }
        ps[qtr][col] = s; pq[qtr][col] = q;
    }
    __syncthreads();
    if (tid < 64) {
        float ss = ps[0][tid] + ps[1][tid] + ps[2][tid] + ps[3][tid];
        float qq = pq[0][tid] + pq[1][tid] + pq[2][tid] + pq[3][tid];
        float mean = ss * (1.0f / 128.0f);
        float var  = qq * (1.0f / 128.0f) - mean * mean;
        mS[tid] = mean;
        rS[tid] = rsqrtf(var + 1e-5f);
    }
    __syncthreads();

    // normalize -> transposed + p16-permuted fp16 in sT
    {
        const int warp = wid;
#pragma unroll 8
        for (int e = 0; e < 32; e++) {
            int gidx = e * 8 + warp;
            int c = (gidx & 15) * 8 + (lane & 7);
            int jj = (gidx >> 4) * 4 + (lane >> 3);
            float v = (__half2float(sOh[c * POH + jj]) - mS[jj]) * rS[jj] * __ldg(ong + c) + __ldg(onb + c);
            sTh[jj * (2 * PW) + p16(c)] = __float2half_rn(v);
        }
    }
    __syncthreads();

    // fp16 GEMM: rows = jj, K = c, B frag-major L1
    float acc[2][4][4];
#pragma unroll
    for (int mf = 0; mf < 2; mf++)
#pragma unroll
        for (int nf = 0; nf < 4; nf++)
#pragma unroll
            for (int v = 0; v < 4; v++) acc[mf][nf][v] = 0.0f;

#pragma unroll
    for (int kg = 0; kg < 8; kg++) {
        int kb = kg * 8;
        uint32_t a[2][4];
#pragma unroll
        for (int mf = 0; mf < 2; mf++) {
            int row = wm * 32 + mf * 16 + lr;
            uint2 lo = *reinterpret_cast<const uint2*>(sTw + row * PW + kb + 2 * lc);
            uint2 hi = *reinterpret_cast<const uint2*>(sTw + (row + 8) * PW + kb + 2 * lc);
            a[mf][0] = lo.x; a[mf][1] = hi.x; a[mf][2] = lo.y; a[mf][3] = hi.y;
        }
#pragma unroll
        for (int nf = 0; nf < 4; nf++) {
            int g = wn * 4 + nf;
            uint2 b = __ldg(WO + g * 256 + kg * 32 + lane);
            mma16h(acc[0][nf], a[0][0], a[0][1], a[0][2], a[0][3], b.x, b.y);
            mma16h(acc[1][nf], a[1][0], a[1][1], a[1][2], a[1][3], b.x, b.y);
        }
    }

    // epilogue: bias + fp16 gate, DIRECT fragment stores (full 32B sectors)
    const size_t grow = (size_t)i * 512 + j0;
#pragma unroll
    for (int mf = 0; mf < 2; mf++) {
#pragma unroll
        for (int nf = 0; nf < 4; nf++) {
            size_t jj = grow + wm * 32 + mf * 16 + lr;
            int col = wn * 32 + nf * 8 + 2 * lc;
            float b0v = __ldg(ob + col), b1v = __ldg(ob + col + 1);
            size_t fi = gate_fi(jj, col);
            float2 gt0 = __half22float2(GATE2[fi]);
            float2 gt1 = __half22float2(GATE2[fi + 32]);
            *reinterpret_cast<float2*>(out + jj * 128 + col) =
                make_float2((acc[mf][nf][0] + b0v) * gt0.x, (acc[mf][nf][1] + b1v) * gt0.y);
            *reinterpret_cast<float2*>(out + (jj + 8) * 128 + col) =
                make_float2((acc[mf][nf][2] + b0v) * gt1.x, (acc[mf][nf][3] + b1v) * gt1.y);
        }
    }
}

// ============================================================
// launch
// ============================================================
extern "C" void kernel_launch(void* const* d_in, const int* in_sizes, int n_in,
                              void* d_out, int out_size) {
    const float* z      = (const float*)d_in[0];
    const float* norm_g = (const float*)d_in[1];
    const float* norm_b = (const float*)d_in[2];
    const float* a_w    = (const float*)d_in[3];
    const float* a_b    = (const float*)d_in[4];
    const float* ag_w   = (const float*)d_in[5];
    const float* ag_b   = (const float*)d_in[6];
    const float* onorm_g= (const float*)d_in[7];
    const float* onorm_b= (const float*)d_in[8];
    const float* o_w    = (const float*)d_in[9];
    const float* o_b    = (const float*)d_in[10];
    const float* g_wp   = (const float*)d_in[11];
    const float* g_bp   = (const float*)d_in[12];
    float* out = (float*)d_out;

    const int SMA = 64 * PW * 4 + 128 * PH * 2;      // 36.9 KB
    const int SMS = 2 * 2 * 128 * PS * 4;            // 81.9 KB
    const int SMC = (128 * (POH / 2) + 64 * PW) * 4; // 36.9 KB

    static bool attr_done = false;
    if (!attr_done) {
        cudaFuncSetAttribute(fusedA,   cudaFuncAttributeMaxDynamicSharedMemorySize, SMA);
        cudaFuncSetAttribute(syrk_mma, cudaFuncAttributeMaxDynamicSharedMemorySize, SMS);
        cudaFuncSetAttribute(fusedC,   cudaFuncAttributeMaxDynamicSharedMemorySize, SMC);
        attr_done = true;
    }

    prep_w<<<32, 512>>>(a_w, ag_w, g_wp, o_w);
    fusedA<<<LL / 64, 256, SMA>>>(z, norm_g, norm_b, a_b, ag_b, g_bp);
    syrk_mma<<<dim3(10, 128), 256, SMS>>>();
    fusedC<<<dim3(8, L), 256, SMC>>>(onorm_g, onorm_b, o_b, out);
}

// round 17
// speedup vs baseline: 1.0585x; 1.0585x over previous
#include <cuda_runtime.h>
#include <cuda_fp16.h>
#include <math.h>
#include <stdint.h>

#define L 512
#define LL (L*L)
#define POH 72   // fusedC fp16 gather pitch in HALVES (144B)
#define PW 72    // fp16 tile pitch in WORDS (144 halves; 72 mod 32 == 8)
#define PH 72    // fusedA fp16 staging pitch in HALVES (144B, 16B-aligned)
#define PS 40    // syrk chunk pitch in WORDS (80 halves per row slot, 64 used)
#define PR 136   // fusedC fp32 result staging pitch (floats)

// ---- scratch (device globals; allocation-free contract) ----
__device__ __half   g_gate[(size_t)LL*128]; // frag-major __half2 layout
__device__ __half   g_at  [(size_t)128*LL]; // gated a, fp16, l-dim pair-permuted
__device__ __half   g_o   [(size_t)128*LL]; // einsum output, fp16
__device__ uint32_t g_awh [8192];           // fp16 weights, frag-major (uint2=4 halves)
__device__ uint32_t g_agwh[8192];
__device__ uint32_t g_gwh [8192];
__device__ uint32_t g_owh [8192];

__device__ __forceinline__ float sigmoidf_(float x) { return 1.0f / (1.0f + expf(-x)); }

// pair/k8 permutation (order 0,4,1,5,2,6,3,7)
__device__ __forceinline__ int kperm(int k) {
    return (k & ~7) | (((k & 3) << 1) | ((k >> 2) & 1));
}
// fp16 k16 pair permutation on halves
__device__ __forceinline__ int p16(int k) {
    return (k & ~15) | (((k >> 1) & 3) << 2) | (((k >> 3) & 1) << 1) | (k & 1);
}
// frag-major __half2 index for gate[(row, col even pair)]
__device__ __forceinline__ size_t gate_fi(size_t row, int col) {
    return ((row >> 4) * 16 + (size_t)(col >> 3)) * 64 +
           ((row >> 3) & 1) * 32 + (row & 7) * 4 + ((col & 7) >> 1);
}

// fp16 m16n8k16, fp32 accum
__device__ __forceinline__ void mma16h(float* c, uint32_t a0, uint32_t a1,
                                       uint32_t a2, uint32_t a3,
                                       uint32_t b0, uint32_t b1) {
    asm volatile(
        "mma.sync.aligned.m16n8k16.row.col.f32.f16.f16.f32 "
        "{%0,%1,%2,%3}, {%4,%5,%6,%7}, {%8,%9}, {%0,%1,%2,%3};\n"
        : "+f"(c[0]), "+f"(c[1]), "+f"(c[2]), "+f"(c[3])
        : "r"(a0), "r"(a1), "r"(a2), "r"(a3), "r"(b0), "r"(b1));
}

__device__ __forceinline__ void cpa16(void* dst, const void* src) {
    uint32_t s = (uint32_t)__cvta_generic_to_shared(dst);
    asm volatile("cp.async.cg.shared.global [%0], [%1], 16;\n" :: "r"(s), "l"(src));
}
__device__ __forceinline__ void cpa_commit() { asm volatile("cp.async.commit_group;\n" ::: "memory"); }
template<int N> __device__ __forceinline__ void cpa_wait() {
    asm volatile("cp.async.wait_group %0;\n" :: "n"(N) : "memory");
}

// ============================================================
// K0: pre-convert weights to fp16, FRAGMENT-MAJOR
// ============================================================
__global__ void prep_w(const float* __restrict__ aw, const float* __restrict__ agw,
                       const float* __restrict__ gw, const float* __restrict__ ow) {
    int idx = blockIdx.x * 512 + threadIdx.x;   // 16384 total (4 x 4096 uint2)
    int w = idx >> 12, i = idx & 4095;
    int lane = i & 31, kg = (i >> 5) & 7, g = i >> 8;
    int lr = lane >> 2, lc = lane & 3;
    const float* src = (w == 0) ? aw : (w == 1) ? agw : (w == 2) ? gw : ow;
    uint32_t* dst = (w == 0) ? g_awh : (w == 1) ? g_agwh : (w == 2) ? g_gwh : g_owh;
    int n = g * 8 + lr, k0 = kg * 16 + 2 * lc;
    __half2 lo = __floats2half2_rn(src[n * 128 + k0],     src[n * 128 + k0 + 1]);
    __half2 hi = __floats2half2_rn(src[n * 128 + k0 + 8], src[n * 128 + k0 + 9]);
    dst[i * 2]     = *reinterpret_cast<uint32_t*>(&lo);
    dst[i * 2 + 1] = *reinterpret_cast<uint32_t*>(&hi);
}

// ============================================================
// K1: fused LN(fp16) + dual fp16 GEMM (a,ag) + gating -> g_at
//     + fp16 gate GEMM. 256 thr, 64-row tile.
// ============================================================
__global__ void __launch_bounds__(256, 2)
fusedA(const float* __restrict__ z, const float* __restrict__ ng, const float* __restrict__ nb,
       const float* __restrict__ ab, const float* __restrict__ agb, const float* __restrict__ gb) {
    extern __shared__ uint32_t sm[];
    uint32_t* sZw = sm;                             // 64 x PW words fp16 zn (p16 layout)
    __half2*  sZ2 = reinterpret_cast<__half2*>(sm);
    __half*   sP  = reinterpret_cast<__half*>(sm + 64 * PW);  // [col 128][row PH]
    const int tid = threadIdx.x;
    const int wid = tid >> 5, lane = tid & 31;
    const int lr = lane >> 2, lc = lane & 3;
    const size_t m0 = (size_t)blockIdx.x * 64;

    const uint2* WA = reinterpret_cast<const uint2*>(g_awh);
    const uint2* WQ = reinterpret_cast<const uint2*>(g_agwh);
    const uint2* WG = reinterpret_cast<const uint2*>(g_gwh);
    __half2* GATE2 = reinterpret_cast<__half2*>(g_gate);

    // LayerNorm: warp w handles rows [8w, 8w+8); z loads batched 4-at-a-time (MLP)
    {
        float4 g4 = reinterpret_cast<const float4*>(ng)[lane];
        float4 b4 = reinterpret_cast<const float4*>(nb)[lane];
        const int pp0 = kperm(2 * lane), pp1 = kperm(2 * lane + 1);
#pragma unroll
        for (int hb = 0; hb < 2; hb++) {
            float4 vb[4];
#pragma unroll
            for (int it = 0; it < 4; it++)
                vb[it] = reinterpret_cast<const float4*>(z)[(m0 + wid * 8 + hb * 4 + it) * 32 + lane];
#pragma unroll
            for (int it = 0; it < 4; it++) {
                int row = wid * 8 + hb * 4 + it;
                float4 v = vb[it];
                float s = v.x + v.y + v.z + v.w;
                float q = v.x*v.x + v.y*v.y + v.z*v.z + v.w*v.w;
#pragma unroll
                for (int o = 16; o > 0; o >>= 1) {
                    s += __shfl_xor_sync(0xffffffffu, s, o);
                    q += __shfl_xor_sync(0xffffffffu, q, o);
                }
                float mean = s * (1.0f / 128.0f);
                float var  = q * (1.0f / 128.0f) - mean * mean;
                float rs   = rsqrtf(var + 1e-5f);
                sZ2[row * PW + pp0] = __floats2half2_rn((v.x - mean) * rs * g4.x + b4.x,
                                                        (v.y - mean) * rs * g4.y + b4.y);
                sZ2[row * PW + pp1] = __floats2half2_rn((v.z - mean) * rs * g4.z + b4.z,
                                                        (v.w - mean) * rs * g4.w + b4.w);
            }
        }
    }
    __syncthreads();

    // ---- dual fp16 GEMM: acc_a = zn@a_w^T, acc_q = zn@ag_w^T ----
    float acc_a[4][2][4], acc_q[4][2][4];
#pragma unroll
    for (int mf = 0; mf < 4; mf++)
#pragma unroll
        for (int nf = 0; nf < 2; nf++)
#pragma unroll
            for (int v = 0; v < 4; v++) { acc_a[mf][nf][v] = 0.0f; acc_q[mf][nf][v] = 0.0f; }

#pragma unroll
    for (int kg = 0; kg < 8; kg++) {
        int kb = kg * 8;
        uint32_t a[4][4];
#pragma unroll
        for (int mf = 0; mf < 4; mf++) {
            int row = mf * 16 + lr;
            uint2 lo = *reinterpret_cast<const uint2*>(sZw + row * PW + kb + 2 * lc);
            uint2 hi = *reinterpret_cast<const uint2*>(sZw + (row + 8) * PW + kb + 2 * lc);
            a[mf][0] = lo.x; a[mf][1] = hi.x; a[mf][2] = lo.y; a[mf][3] = hi.y;
        }
#pragma unroll
        for (int nf = 0; nf < 2; nf++) {
            int g = wid * 2 + nf;
            uint2 ba = __ldg(WA + g * 256 + kg * 32 + lane);
            uint2 bq = __ldg(WQ + g * 256 + kg * 32 + lane);
#pragma unroll
            for (int mf = 0; mf < 4; mf++) {
                mma16h(acc_a[mf][nf], a[mf][0], a[mf][1], a[mf][2], a[mf][3], ba.x, ba.y);
                mma16h(acc_q[mf][nf], a[mf][0], a[mf][1], a[mf][2], a[mf][3], bq.x, bq.y);
            }
        }
    }

    // epilogue: P = (a + ab) * sigmoid(q + agb) -> fp16 staged in sP (pair-perm rows)
#pragma unroll
    for (int nf = 0; nf < 2; nf++) {
        int col = wid * 16 + nf * 8 + 2 * lc;
        float ba0 = __ldg(ab + col),  ba1 = __ldg(ab + col + 1);
        float bq0 = __ldg(agb + col), bq1 = __ldg(agb + col + 1);
#pragma unroll
        for (int mf = 0; mf < 4; mf++) {
            int r0 = p16(mf * 16 + lr), r1 = p16(mf * 16 + 8 + lr);
            sP[col * PH + r0]       = __float2half_rn((acc_a[mf][nf][0] + ba0) * sigmoidf_(acc_q[mf][nf][0] + bq0));
            sP[(col + 1) * PH + r0] = __float2half_rn((acc_a[mf][nf][1] + ba1) * sigmoidf_(acc_q[mf][nf][1] + bq1));
            sP[col * PH + r1]       = __float2half_rn((acc_a[mf][nf][2] + ba0) * sigmoidf_(acc_q[mf][nf][2] + bq0));
            sP[(col + 1) * PH + r1] = __float2half_rn((acc_a[mf][nf][3] + ba1) * sigmoidf_(acc_q[mf][nf][3] + bq1));
        }
    }
    __syncthreads();

    // coalesced uint4 store of fp16 a-tile: 128 cols x 64 halves
#pragma unroll
    for (int e = 0; e < 4; e++) {
        int idx = tid + 256 * e;           // 1024 uint4
        int c = idx >> 3, e8 = idx & 7;    // 8 uint4 per col
        uint4 v = *reinterpret_cast<const uint4*>(sP + c * PH + e8 * 8);
        *reinterpret_cast<uint4*>(g_at + (size_t)c * LL + m0 + e8 * 8) = v;
    }

    // ---- fp16 gate GEMM (sZ unmodified) ----
    float acc_g[4][2][4];
#pragma unroll
    for (int mf = 0; mf < 4; mf++)
#pragma unroll
        for (int nf = 0; nf < 2; nf++)
#pragma unroll
            for (int v = 0; v < 4; v++) acc_g[mf][nf][v] = 0.0f;

#pragma unroll
    for (int kg = 0; kg < 8; kg++) {
        int kb = kg * 8;
        uint32_t a[4][4];
#pragma unroll
        for (int mf = 0; mf < 4; mf++) {
            int row = mf * 16 + lr;
            uint2 lo = *reinterpret_cast<const uint2*>(sZw + row * PW + kb + 2 * lc);
            uint2 hi = *reinterpret_cast<const uint2*>(sZw + (row + 8) * PW + kb + 2 * lc);
            a[mf][0] = lo.x; a[mf][1] = hi.x; a[mf][2] = lo.y; a[mf][3] = hi.y;
        }
#pragma unroll
        for (int nf = 0; nf < 2; nf++) {
            int g = wid * 2 + nf;
            uint2 bg = __ldg(WG + g * 256 + kg * 32 + lane);
#pragma unroll
            for (int mf = 0; mf < 4; mf++)
                mma16h(acc_g[mf][nf], a[mf][0], a[mf][1], a[mf][2], a[mf][3], bg.x, bg.y);
        }
    }

    // gate stored frag-major fp16 (coalesced __half2)
#pragma unroll
    for (int nf = 0; nf < 2; nf++) {
        int col = wid * 16 + nf * 8 + 2 * lc;
        float b0v = __ldg(gb + col), b1v = __ldg(gb + col + 1);
#pragma unroll
        for (int mf = 0; mf < 4; mf++) {
            size_t row = m0 + mf * 16 + lr;
            size_t fi = gate_fi(row, col);
            GATE2[fi]      = __floats2half2_rn(sigmoidf_(acc_g[mf][nf][0] + b0v),
                                               sigmoidf_(acc_g[mf][nf][1] + b1v));
            GATE2[fi + 32] = __floats2half2_rn(sigmoidf_(acc_g[mf][nf][2] + b0v),
                                               sigmoidf_(acc_g[mf][nf][3] + b1v));
        }
    }
}

// ============================================================
// K2: fp16 SYRK per channel (m16n8k16, fp32 accum), cp.async
//     double-buffered, k-chunk 64. fp16 output, mirror staged
//     through smem for coalesced stores. 256 thr.
// ============================================================
__global__ void __launch_bounds__(256, 2)
syrk_mma() {
    extern __shared__ uint32_t sm[];   // 2 stages x (A + B), pitch PS words/row
    const int tid  = threadIdx.x;
    const int wid  = tid >> 5, lane = tid & 31;
    const int wm   = wid >> 1, wn = wid & 1;
    const int lr   = lane >> 2, lc = lane & 3;

    const int c = blockIdx.y;
    int rem = blockIdx.x, bi = 0, span = 4;
    while (rem >= span) { rem -= span; span--; bi++; }
    int bj = bi + rem;
    const int i0 = bi * 128, j0 = bj * 128;
    const bool diag = (bi == bj);

    const __half* __restrict__ Ag = g_at + (size_t)c * LL;
    __half* __restrict__ O = g_o + (size_t)c * LL;

    const int STG_SZ = 2 * 128 * PS;   // words per stage (A+B)

    auto load_chunk = [&](int kc, int buf) {
        uint32_t* sA = sm + buf * STG_SZ;
        uint32_t* sB = sA + 128 * PS;
#pragma unroll
        for (int e = 0; e < 4; e++) {
            int idx = tid + 256 * e;
            int r = idx >> 3, c8 = idx & 7;
            cpa16(sA + r * PS + c8 * 4, Ag + (size_t)(i0 + r) * 512 + kc * 64 + c8 * 8);
            if (!diag)
                cpa16(sB + r * PS + c8 * 4, Ag + (size_t)(j0 + r) * 512 + kc * 64 + c8 * 8);
        }
        cpa_commit();
    };

    float acc[2][8][4];
#pragma unroll
    for (int mf = 0; mf < 2; mf++)
#pragma unroll
        for (int nf = 0; nf < 8; nf++)
#pragma unroll
            for (int v = 0; v < 4; v++) acc[mf][nf][v] = 0.0f;

    load_chunk(0, 0);

    for (int kc = 0; kc < 8; kc++) {
        if (kc + 1 < 8) { load_chunk(kc + 1, (kc + 1) & 1); cpa_wait<1>(); }
        else            { cpa_wait<0>(); }
        __syncthreads();
        const uint32_t* sA = sm + (kc & 1) * STG_SZ;
        const uint32_t* sB = diag ? sA : sA + 128 * PS;
#pragma unroll
        for (int g = 0; g < 4; g++) {
            int kb = g * 8;
            uint32_t a[2][4];
#pragma unroll
            for (int mf = 0; mf < 2; mf++) {
                int row = wm * 32 + mf * 16 + lr;
                uint2 lo = *reinterpret_cast<const uint2*>(sA + row * PS + kb + 2 * lc);
                uint2 hi = *reinterpret_cast<const uint2*>(sA + (row + 8) * PS + kb + 2 * lc);
                a[mf][0] = lo.x; a[mf][1] = hi.x; a[mf][2] = lo.y; a[mf][3] = hi.y;
            }
#pragma unroll
            for (int nf = 0; nf < 8; nf++) {
                int col = wn * 64 + nf * 8 + lr;
                uint2 b = *reinterpret_cast<const uint2*>(sB + col * PS + kb + 2 * lc);
                mma16h(acc[0][nf], a[0][0], a[0][1], a[0][2], a[0][3], b.x, b.y);
                mma16h(acc[1][nf], a[1][0], a[1][1], a[1][2], a[1][3], b.x, b.y);
            }
        }
        __syncthreads();
    }

    // direct tile write (fp16 __half2)
#pragma unroll
    for (int mf = 0; mf < 2; mf++) {
#pragma unroll
        for (int nf = 0; nf < 8; nf++) {
            int rowi = i0 + wm * 32 + mf * 16 + lr;
            int colj = j0 + wn * 64 + nf * 8 + 2 * lc;
            *reinterpret_cast<__half2*>(O + (size_t)rowi * 512 + colj) =
                __floats2half2_rn(acc[mf][nf][0], acc[mf][nf][1]);
            *reinterpret_cast<__half2*>(O + (size_t)(rowi + 8) * 512 + colj) =
                __floats2half2_rn(acc[mf][nf][2], acc[mf][nf][3]);
        }
    }

    // mirror: stage transposed fp16 tile in smem, then coalesced uint4 stores
    if (!diag) {
        __half* st = reinterpret_cast<__half*>(sm);   // [col 128][row], pitch 136 halves
#pragma unroll
        for (int mf = 0; mf < 2; mf++) {
#pragma unroll
            for (int nf = 0; nf < 8; nf++) {
                int r  = wm * 32 + mf * 16 + lr;
                int cA = wn * 64 + nf * 8 + 2 * lc;
                st[cA * 136 + r]           = __float2half_rn(acc[mf][nf][0]);
                st[(cA + 1) * 136 + r]     = __float2half_rn(acc[mf][nf][1]);
                st[cA * 136 + r + 8]       = __float2half_rn(acc[mf][nf][2]);
                st[(cA + 1) * 136 + r + 8] = __float2half_rn(acc[mf][nf][3]);
            }
        }
        __syncthreads();
#pragma unroll
        for (int e = 0; e < 8; e++) {
            int idx = tid + 256 * e;        // 2048 uint4
            int col = idx >> 4, e8 = idx & 15;
            uint4 v = *reinterpret_cast<const uint4*>(st + col * 136 + e8 * 8);
            *reinterpret_cast<uint4*>(O + (size_t)(j0 + col) * 512 + i0 + e8 * 8) = v;
        }
    }
}

// ============================================================
// K3: fused gather (fp16 smem, cp.async) + channel-LN + fp16
//     projection + fp16 gating. fp32 staging for fully-merged
//     128B-line output stores.
// ============================================================
__global__ void __launch_bounds__(256, 3)
fusedC(const float* __restrict__ ong, const float* __restrict__ onb,
       const float* __restrict__ ob, float* __restrict__ out) {
    extern __shared__ uint32_t sm[];
    __half*   sOh = reinterpret_cast<__half*>(sm);  // [c 128][jj 64], pitch POH halves
    uint32_t* sTw = sm + 128 * (POH / 2);           // fp16 [jj 64][p16 c], pitch PW words
    __half*   sTh = reinterpret_cast<__half*>(sTw);
    __shared__ float ps[4][64], pq[4][64], mS[64], rS[64];

    const int tid = threadIdx.x;
    const int wid = tid >> 5, lane = tid & 31;
    const int wm = wid >> 2, wn = wid & 3;
    const int lr = lane >> 2, lc = lane & 3;
    const int i = blockIdx.y, j0 = blockIdx.x * 64;

    const uint2* WO = reinterpret_cast<const uint2*>(g_owh);
    const __half2* GATE2 = reinterpret_cast<const __half2*>(g_gate);

    // gather o tile [c][jj] fp16 via cp.async (deep MLP)
#pragma unroll
    for (int e = 0; e < 4; e++) {
        int idx = tid + 256 * e;       // 1024 x 16B
        int c = idx >> 3, j8 = idx & 7;
        cpa16(sOh + c * POH + j8 * 8, g_o + (size_t)c * LL + (size_t)i * 512 + j0 + j8 * 8);
    }
    cpa_commit();
    cpa_wait<0>();
    __syncthreads();

    // channel reduce (convert fp16 on the fly)
    {
        int col = tid & 63, qtr = tid >> 6;
        float s = 0.0f, q = 0.0f;
#pragma unroll 8
        for (int c = qtr * 32; c < qtr * 32 + 32; c++) {
            float v = __half2float(sOh[c * POH + col]);
            s += v; q += v * v;
        }
        ps[qtr][col] = s; pq[qtr][col] = q;
    }
    __syncthreads();
    if (tid < 64) {
        float ss = ps[0][tid] + ps[1][tid] + ps[2][tid] + ps[3][tid];
        float qq = pq[0][tid] + pq[1][tid] + pq[2][tid] + pq[3][tid];
        float mean = ss * (1.0f / 128.0f);
        float var  = qq * (1.0f / 128.0f) - mean * mean;
        mS[tid] = mean;
        rS[tid] = rsqrtf(var + 1e-5f);
    }
    __syncthreads();

    // normalize -> transposed + p16-permuted fp16 in sT
    {
        const int warp = wid;
#pragma unroll 8
        for (int e = 0; e < 32; e++) {
            int gidx = e * 8 + warp;
            int c = (gidx & 15) * 8 + (lane & 7);
            int jj = (gidx >> 4) * 4 + (lane >> 3);
            float v = (__half2float(sOh[c * POH + jj]) - mS[jj]) * rS[jj] * __ldg(ong + c) + __ldg(onb + c);
            sTh[jj * (2 * PW) + p16(c)] = __float2half_rn(v);
        }
    }
    __syncthreads();

    // fp16 GEMM: rows = jj, K = c, B frag-major L1
    float acc[2][4][4];
#pragma unroll
    for (int mf = 0; mf < 2; mf++)
#pragma unroll
        for (int nf = 0; nf < 4; nf++)
#pragma unroll
            for (int v = 0; v < 4; v++) acc[mf][nf][v] = 0.0f;

#pragma unroll
    for (int kg = 0; kg < 8; kg++) {
        int kb = kg * 8;
        uint32_t a[2][4];
#pragma unroll
        for (int mf = 0; mf < 2; mf++) {
            int row = wm * 32 + mf * 16 + lr;
            uint2 lo = *reinterpret_cast<const uint2*>(sTw + row * PW + kb + 2 * lc);
            uint2 hi = *reinterpret_cast<const uint2*>(sTw + (row + 8) * PW + kb + 2 * lc);
            a[mf][0] = lo.x; a[mf][1] = hi.x; a[mf][2] = lo.y; a[mf][3] = hi.y;
        }
#pragma unroll
        for (int nf = 0; nf < 4; nf++) {
            int g = wn * 4 + nf;
            uint2 b = __ldg(WO + g * 256 + kg * 32 + lane);
            mma16h(acc[0][nf], a[0][0], a[0][1], a[0][2], a[0][3], b.x, b.y);
            mma16h(acc[1][nf], a[1][0], a[1][1], a[1][2], a[1][3], b.x, b.y);
        }
    }
    __syncthreads();   // smem free; reuse as fp32 output stage

    // epilogue: bias + fp16 gate (frag-major), stage fp32 into sR
    const size_t grow = (size_t)i * 512 + j0;
    float* sR = reinterpret_cast<float*>(sm);       // pitch PR floats, 64 rows
#pragma unroll
    for (int mf = 0; mf < 2; mf++) {
#pragma unroll
        for (int nf = 0; nf < 4; nf++) {
            int jj = wm * 32 + mf * 16 + lr;
            int col = wn * 32 + nf * 8 + 2 * lc;
            float b0v = __ldg(ob + col), b1v = __ldg(ob + col + 1);
            size_t fi = gate_fi(grow + jj, col);
            float2 gt0 = __half22float2(GATE2[fi]);
            float2 gt1 = __half22float2(GATE2[fi + 32]);
            *reinterpret_cast<float2*>(sR + jj * PR + col) =
                make_float2((acc[mf][nf][0] + b0v) * gt0.x, (acc[mf][nf][1] + b1v) * gt0.y);
            *reinterpret_cast<float2*>(sR + (jj + 8) * PR + col) =
                make_float2((acc[mf][nf][2] + b0v) * gt1.x, (acc[mf][nf][3] + b1v) * gt1.y);
        }
    }
    __syncthreads();

    // coalesced output store (full 128B lines per warp)
#pragma unroll 4
    for (int e = 0; e < 16; e++) {
        int idx = tid + 256 * e;
        int jj = idx >> 6, c2 = idx & 63;
        float2 v = *reinterpret_cast<const float2*>(sR + jj * PR + 2 * c2);
        *reinterpret_cast<float2*>(out + (grow + jj) * 128 + 2 * c2) = v;
    }
}

// ============================================================
// launch
// ============================================================
extern "C" void kernel_launch(void* const* d_in, const int* in_sizes, int n_in,
                              void* d_out, int out_size) {
    const float* z      = (const float*)d_in[0];
    const float* norm_g = (const float*)d_in[1];
    const float* norm_b = (const float*)d_in[2];
    const float* a_w    = (const float*)d_in[3];
    const float* a_b    = (const float*)d_in[4];
    const float* ag_w   = (const float*)d_in[5];
    const float* ag_b   = (const float*)d_in[6];
    const float* onorm_g= (const float*)d_in[7];
    const float* onorm_b= (const float*)d_in[8];
    const float* o_w    = (const float*)d_in[9];
    const float* o_b    = (const float*)d_in[10];
    const float* g_wp   = (const float*)d_in[11];
    const float* g_bp   = (const float*)d_in[12];
    float* out = (float*)d_out;

    const int SMA = 64 * PW * 4 + 128 * PH * 2;      // 36.9 KB
    const int SMS = 2 * 2 * 128 * PS * 4;            // 81.9 KB
    const int SMC = (128 * (POH / 2) + 64 * PW) * 4; // 36.9 KB (>= 64*PR*4 stage)

    static bool attr_done = false;
    if (!attr_done) {
        cudaFuncSetAttribute(fusedA,   cudaFuncAttributeMaxDynamicSharedMemorySize, SMA);
        cudaFuncSetAttribute(syrk_mma, cudaFuncAttributeMaxDynamicSharedMemorySize, SMS);
        cudaFuncSetAttribute(fusedC,   cudaFuncAttributeMaxDynamicSharedMemorySize, SMC);
        attr_done = true;
    }

    prep_w<<<32, 512>>>(a_w, ag_w, g_wp, o_w);
    fusedA<<<LL / 64, 256, SMA>>>(z, norm_g, norm_b, a_b, ag_b, g_bp);
    syrk_mma<<<dim3(10, 128), 256, SMS>>>();
    fusedC<<<dim3(8, L), 256, SMC>>>(onorm_g, onorm_b, o_b, out);
}